// round 12
// baseline (speedup 1.0000x reference)
#include <cuda_runtime.h>
#include <cuda_fp16.h>
#include <cstdint>

#define D 64
#define H 128
#define NMAX 50048

__device__ __align__(16) __half g_P[(size_t)NMAX * H];
__device__ __align__(16) __half g_Q[(size_t)NMAX * H];
__device__ int g_ctr_pre;    // reset by edge_kernel (for next replay)
__device__ int g_ctr_edge;   // reset by precompute_kernel (runs first)

__device__ __forceinline__ float sigt(float x) {
    float t;
    asm("tanh.approx.f32 %0, %1;" : "=f"(t) : "f"(x * 0.5f));
    return fmaf(t, 0.5f, 0.5f);
}
__device__ __forceinline__ uint32_t sigt2u(uint32_t p, uint32_t q) {
    __half2 x = __hadd2(*(__half2*)&p, *(__half2*)&q);
    const __half2 hhalf = __floats2half2_rn(0.5f, 0.5f);
    __half2 xh = __hmul2(x, hhalf);
    uint32_t tu;
    asm("tanh.approx.f16x2 %0, %1;" : "=r"(tu) : "r"(*(uint32_t*)&xh));
    __half2 r = __hfma2(*(__half2*)&tu, hhalf, hhalf);
    return *(uint32_t*)&r;
}
__device__ __forceinline__ uint32_t f16x2(float lo, float hi) {
    __half2 h = __floats2half2_rn(lo, hi);
    return *(uint32_t*)&h;
}

__device__ __forceinline__ void mma_f16(float* c, uint4 a, uint2 b) {
    asm volatile(
        "mma.sync.aligned.m16n8k16.row.col.f32.f16.f16.f32 "
        "{%0,%1,%2,%3}, {%4,%5,%6,%7}, {%8,%9}, {%0,%1,%2,%3};"
        : "+f"(c[0]), "+f"(c[1]), "+f"(c[2]), "+f"(c[3])
        : "r"(a.x), "r"(a.y), "r"(a.z), "r"(a.w), "r"(b.x), "r"(b.y));
}

// Build fp16 A-fragments (m16n8k16 row-major layout, validated R5-R11).
__device__ __forceinline__ void build_frags_h(const float* scr, uint4* A,
                                              int mt_base, int nkt, int t, int nth)
{
    const int ncols = nkt * 16;
    for (int fid = t; fid < 64 * nkt; fid += nth) {
        int fl = fid & 31;
        int kt = (fid >> 5) % nkt;
        int mtl = fid / (32 * nkt);
        int fg = fl >> 2, ft = fl & 3;
        int lr0 = mtl * 16 + fg, lr1 = lr0 + 8;
        int k0 = kt * 16 + ft * 2;
        uint4 hi;
        hi.x = f16x2(scr[lr0 * ncols + k0],     scr[lr0 * ncols + k0 + 1]);
        hi.y = f16x2(scr[lr1 * ncols + k0],     scr[lr1 * ncols + k0 + 1]);
        hi.z = f16x2(scr[lr0 * ncols + k0 + 8], scr[lr0 * ncols + k0 + 9]);
        hi.w = f16x2(scr[lr1 * ncols + k0 + 8], scr[lr1 * ncols + k0 + 9]);
        A[((mt_base + mtl) * nkt + kt) * 32 + fl] = hi;
    }
}

// Writer XOR = e>>2; reader uses lane ^ (2*nt + lane>>4). Validated R6-R11.
__device__ __forceinline__ void stage4u(uint32_t* B, int nt, int nn, int xe, int k,
                                        uint32_t h01, uint32_t h23)
{
    int kt = k >> 4, kq = (k & 7) >> 1, reg = (k >> 3) & 1;
    int l0 = (nn * 4 + kq) ^ xe, l1 = (nn * 4 + kq + 1) ^ xe;
    int base = (nt * 8 + kt) * 64;
    B[base + l0 * 2 + reg] = h01;
    B[base + l1 * 2 + reg] = h23;
}
__device__ __forceinline__ void stage4h(uint32_t* B, int nt, int nn, int xe, int k,
                                        float z0, float z1, float z2, float z3)
{
    stage4u(B, nt, nn, xe, k, f16x2(z0, z1), f16x2(z2, z3));
}
__device__ __forceinline__ void pair_bar(int pair) {
    asm volatile("bar.sync %0, 64;" :: "r"(1 + pair) : "memory");
}

// ---------------------------------------------------------------------------
// Precompute (unchanged from R10/R11 — ~20us, known good)
// ---------------------------------------------------------------------------
#define P_A1 0
#define P_A2 32768
#define P_B  49152
#define P_B1S 114688
#define PRE_SMEM_BYTES 115712

__global__ void __launch_bounds__(256) precompute_kernel(
    const float* __restrict__ h1, const float* __restrict__ h2,
    const float* __restrict__ W1, const float* __restrict__ b1, int n)
{
    extern __shared__ char smc[];
    uint4* A1 = (uint4*)(smc + P_A1);
    uint4* A2 = (uint4*)(smc + P_A2);
    float* b1s = (float*)(smc + P_B1S);

    const int t = threadIdx.x, lane = t & 31, w = t >> 5;
    const int gid = lane >> 2, tig = lane & 3;

    if (blockIdx.x == 0 && t == 0) g_ctr_edge = 0;

    {
        float* scr = (float*)(smc + P_B);
        for (int chunk = 0; chunk < 4; ++chunk) {
            const int R0 = chunk * 32;
            __syncthreads();
            for (int idx = t; idx < 4096; idx += 256) {
                int r = idx >> 7, k = idx & 127;
                float v;
                if (k < 64) v = W1[(R0 + r) * 256 + k];
                else        v = W1[(R0 + r) * 256 + 64 + k] + W1[(R0 + r) * 256 + 128 + k];
                scr[r * 128 + k] = v;
            }
            __syncthreads();
            build_frags_h(scr, A1, chunk * 2, 8, t, 256);
        }
        for (int chunk = 0; chunk < 4; ++chunk) {
            const int R0 = chunk * 32;
            __syncthreads();
            for (int idx = t; idx < 2048; idx += 256) {
                int r = idx >> 6, k = idx & 63;
                scr[r * 64 + k] = W1[(R0 + r) * 256 + 64 + k];
            }
            __syncthreads();
            build_frags_h(scr, A2, chunk * 2, 4, t, 256);
        }
    }
    if (t < 128) b1s[t] = b1[t];
    __syncthreads();

    float b1r0[8], b1r1[8];
    #pragma unroll
    for (int mt = 0; mt < 8; ++mt) {
        b1r0[mt] = b1s[mt * 16 + gid];
        b1r1[mt] = b1s[mt * 16 + gid + 8];
    }

    uint32_t* Bw = (uint32_t*)(smc + P_B + w * 8192);
    const int e = lane, nt_e = e >> 3, n_e = e & 7, xe = e >> 2;
    const int lq = lane >> 4;
    const int ntiles = (n + 31) >> 5;

    for (;;) {
        int tile;
        if (lane == 0) tile = atomicAdd(&g_ctr_pre, 1);
        tile = __shfl_sync(0xffffffffu, tile, 0);
        if (tile >= ntiles) break;
        const int nb = tile * 32;
        const int node = nb + e;
        __syncwarp();

        if (node < n) {
            const float4* H1 = (const float4*)(h1 + (size_t)node * D);
            const float4* H2 = (const float4*)(h2 + (size_t)node * D);
            #pragma unroll 8
            for (int u = 0; u < 16; ++u) {
                float4 v = H1[u];
                stage4h(Bw, nt_e, n_e, xe, u * 4, v.x, v.y, v.z, v.w);
            }
            #pragma unroll 8
            for (int u = 0; u < 16; ++u) {
                float4 v = H2[u];
                stage4h(Bw, nt_e, n_e, xe, 64 + u * 4, v.x, v.y, v.z, v.w);
            }
        } else {
            #pragma unroll 8
            for (int u = 0; u < 32; ++u)
                stage4h(Bw, nt_e, n_e, xe, u * 4, 0.f, 0.f, 0.f, 0.f);
        }
        __syncwarp();

        float acc[8][4][4];

        #pragma unroll
        for (int mt = 0; mt < 8; ++mt)
            #pragma unroll
            for (int nt = 0; nt < 4; ++nt)
                #pragma unroll
                for (int r = 0; r < 4; ++r) acc[mt][nt][r] = 0.f;

        #pragma unroll 1
        for (int kt = 0; kt < 8; ++kt) {
            uint2 bh[4];
            #pragma unroll
            for (int nt = 0; nt < 4; ++nt)
                bh[nt] = ((const uint2*)Bw)[(nt * 8 + kt) * 32 + (lane ^ (2 * nt + lq))];
            #pragma unroll
            for (int mt = 0; mt < 8; ++mt) {
                uint4 ah = A1[(mt * 8 + kt) * 32 + lane];
                #pragma unroll
                for (int nt = 0; nt < 4; ++nt) mma_f16(acc[mt][nt], ah, bh[nt]);
            }
        }
        #pragma unroll
        for (int nt = 0; nt < 4; ++nt) {
            int n0 = nb + nt * 8 + tig * 2, n1 = n0 + 1;
            #pragma unroll
            for (int mt = 0; mt < 8; ++mt) {
                int r0 = mt * 16 + gid, r1 = r0 + 8;
                if (n0 < n) {
                    g_P[(size_t)n0 * H + r0] = __float2half_rn(acc[mt][nt][0] + b1r0[mt]);
                    g_P[(size_t)n0 * H + r1] = __float2half_rn(acc[mt][nt][2] + b1r1[mt]);
                }
                if (n1 < n) {
                    g_P[(size_t)n1 * H + r0] = __float2half_rn(acc[mt][nt][1] + b1r0[mt]);
                    g_P[(size_t)n1 * H + r1] = __float2half_rn(acc[mt][nt][3] + b1r1[mt]);
                }
            }
        }

        #pragma unroll
        for (int mt = 0; mt < 8; ++mt)
            #pragma unroll
            for (int nt = 0; nt < 4; ++nt)
                #pragma unroll
                for (int r = 0; r < 4; ++r) acc[mt][nt][r] = 0.f;

        #pragma unroll 1
        for (int kt = 0; kt < 4; ++kt) {
            uint2 bh[4];
            #pragma unroll
            for (int nt = 0; nt < 4; ++nt)
                bh[nt] = ((const uint2*)Bw)[(nt * 8 + kt) * 32 + (lane ^ (2 * nt + lq))];
            #pragma unroll
            for (int mt = 0; mt < 8; ++mt) {
                uint4 ah = A2[(mt * 4 + kt) * 32 + lane];
                #pragma unroll
                for (int nt = 0; nt < 4; ++nt) mma_f16(acc[mt][nt], ah, bh[nt]);
            }
        }
        #pragma unroll
        for (int nt = 0; nt < 4; ++nt) {
            int n0 = nb + nt * 8 + tig * 2, n1 = n0 + 1;
            #pragma unroll
            for (int mt = 0; mt < 8; ++mt) {
                int r0 = mt * 16 + gid, r1 = r0 + 8;
                if (n0 < n) {
                    g_Q[(size_t)n0 * H + r0] = __float2half_rn(acc[mt][nt][0]);
                    g_Q[(size_t)n0 * H + r1] = __float2half_rn(acc[mt][nt][2]);
                }
                if (n1 < n) {
                    g_Q[(size_t)n1 * H + r0] = __float2half_rn(acc[mt][nt][1]);
                    g_Q[(size_t)n1 * H + r1] = __float2half_rn(acc[mt][nt][3]);
                }
            }
        }
    }
}

// ---------------------------------------------------------------------------
// Edge kernel: warp-PAIR per 32-edge tile. Each warp: half the M rows
// (acc = 64 regs) and half the k-range staging. Named-barrier pair sync.
// Block = 128 threads (2 pairs); low regs -> multiple blocks/SM.
// ---------------------------------------------------------------------------
#define E_A    0                // 32 KB
#define E_B    32768            // 2 pairs x 8 KB
#define E_B2S  49152            // 512 B
#define E_W3S  49664            // 512 B
#define E_PART 50176            // 2 pairs x 64 floats = 512 B
#define E_TK   50688            // 2 ints
#define EDGE_SMEM_BYTES 50816

__global__ void __launch_bounds__(128) edge_kernel(
    const int* __restrict__ src, const int* __restrict__ dst,
    const float* __restrict__ W2, const float* __restrict__ b2,
    const float* __restrict__ W3, const float* __restrict__ b3,
    float* __restrict__ out, int E, int n)
{
    extern __shared__ char smc[];
    uint4* Ahi = (uint4*)(smc + E_A);
    float* b2s = (float*)(smc + E_B2S);
    float* w3s = (float*)(smc + E_W3S);
    int* ptk = (int*)(smc + E_TK);

    const int t = threadIdx.x, lane = t & 31, w = t >> 5;
    const int pair = w >> 1, wp = w & 1;      // pair id, warp-in-pair
    const int gid = lane >> 2, tig = lane & 3;

    if (blockIdx.x == 0 && t == 0) g_ctr_pre = 0;

    // Build W2 fp16 fragments once (scratch reuses B region, 16KB fits).
    {
        float* scr = (float*)(smc + E_B);
        for (int chunk = 0; chunk < 4; ++chunk) {
            __syncthreads();
            for (int i = t; i < 1024; i += 128)
                ((float4*)scr)[i] = ((const float4*)W2)[chunk * 1024 + i];
            __syncthreads();
            build_frags_h(scr, Ahi, chunk * 2, 8, t, 128);
        }
    }
    b2s[t] = b2[t];
    w3s[t] = W3[t];
    __syncthreads();

    // this warp's M-half: mt groups wp*4 .. wp*4+3
    float b2r0[4], b2r1[4], w3r0[4], w3r1[4];
    #pragma unroll
    for (int m = 0; m < 4; ++m) {
        int mt = wp * 4 + m;
        b2r0[m] = b2s[mt * 16 + gid];
        b2r1[m] = b2s[mt * 16 + gid + 8];
        w3r0[m] = w3s[mt * 16 + gid];
        w3r1[m] = w3s[mt * 16 + gid + 8];
    }
    const float b3v = b3[0];

    uint32_t* Bp = (uint32_t*)(smc + E_B + pair * 8192);       // pair-shared
    float* part = (float*)(smc + E_PART) + pair * 64;          // [2][32]
    const int e = lane, nt_e = e >> 3, n_e = e & 7, xe = e >> 2;
    const int lq = lane >> 4;
    const int khalf = wp * 64;                                  // staged k range
    const int ntiles = (E + 31) >> 5;

    for (;;) {
        if (wp == 0 && lane == 0) ptk[pair] = atomicAdd(&g_ctr_edge, 1);
        pair_bar(pair);
        const int tile = ptk[pair];
        if (tile >= ntiles) break;
        const int e0 = tile * 32;
        const int ge = e0 + e;

        // ---- stage this warp's k-half of z1 for edge e=lane
        if (ge < E) {
            int s = min(max(src[ge], 0), n - 1);
            int d = min(max(dst[ge], 0), n - 1);
            const uint4* Pp = (const uint4*)(g_P + (size_t)s * H + khalf);
            const uint4* Qp = (const uint4*)(g_Q + (size_t)d * H + khalf);
            #pragma unroll 4
            for (int u = 0; u < 8; ++u) {
                uint4 pv = Pp[u], qv = Qp[u];
                stage4u(Bp, nt_e, n_e, xe, khalf + u * 8,
                        sigt2u(pv.x, qv.x), sigt2u(pv.y, qv.y));
                stage4u(Bp, nt_e, n_e, xe, khalf + u * 8 + 4,
                        sigt2u(pv.z, qv.z), sigt2u(pv.w, qv.w));
            }
        } else {
            #pragma unroll 8
            for (int u = 0; u < 16; ++u)
                stage4u(Bp, nt_e, n_e, xe, khalf + u * 4, 0u, 0u);
        }
        pair_bar(pair);   // B complete (both halves)

        // ---- MMA over full K, this warp's 4 mt groups
        float acc[4][4][4];
        #pragma unroll
        for (int m = 0; m < 4; ++m)
            #pragma unroll
            for (int nt = 0; nt < 4; ++nt)
                #pragma unroll
                for (int r = 0; r < 4; ++r) acc[m][nt][r] = 0.f;

        #pragma unroll 1
        for (int kt = 0; kt < 8; ++kt) {
            uint2 bh[4];
            #pragma unroll
            for (int nt = 0; nt < 4; ++nt)
                bh[nt] = ((const uint2*)Bp)[(nt * 8 + kt) * 32 + (lane ^ (2 * nt + lq))];
            #pragma unroll
            for (int m = 0; m < 4; ++m) {
                uint4 ah = Ahi[((wp * 4 + m) * 8 + kt) * 32 + lane];
                #pragma unroll
                for (int nt = 0; nt < 4; ++nt) mma_f16(acc[m][nt], ah, bh[nt]);
            }
        }

        // ---- partial epilogue: sigmoid + W3 dot over this warp's 64 rows
        #pragma unroll
        for (int nt = 0; nt < 4; ++nt) {
            float s0 = 0.f, s1 = 0.f;
            #pragma unroll
            for (int m = 0; m < 4; ++m) {
                s0 += sigt(acc[m][nt][0] + b2r0[m]) * w3r0[m]
                    + sigt(acc[m][nt][2] + b2r1[m]) * w3r1[m];
                s1 += sigt(acc[m][nt][1] + b2r0[m]) * w3r0[m]
                    + sigt(acc[m][nt][3] + b2r1[m]) * w3r1[m];
            }
            #pragma unroll
            for (int off = 4; off <= 16; off <<= 1) {
                s0 += __shfl_xor_sync(0xffffffffu, s0, off);
                s1 += __shfl_xor_sync(0xffffffffu, s1, off);
            }
            if (gid == 0) {
                part[wp * 32 + nt * 8 + tig * 2] = s0;
                part[wp * 32 + nt * 8 + tig * 2 + 1] = s1;
            }
        }
        pair_bar(pair);   // partials ready; also guards B reuse next tile

        if (wp == 0) {
            int go = e0 + lane;
            if (go < E) out[go] = part[lane] + part[32 + lane] + b3v;
        }
    }
}

extern "C" void kernel_launch(void* const* d_in, const int* in_sizes, int n_in,
                              void* d_out, int out_size)
{
    const float* h1 = (const float*)d_in[0];
    const float* h2 = (const float*)d_in[1];
    const int* src = (const int*)d_in[2];
    const int* dst = (const int*)d_in[3];
    const float* W1 = (const float*)d_in[4];
    const float* b1 = (const float*)d_in[5];
    const float* W2 = (const float*)d_in[6];
    const float* b2 = (const float*)d_in[7];
    const float* W3 = (const float*)d_in[8];
    const float* b3 = (const float*)d_in[9];
    float* out = (float*)d_out;

    const int n = in_sizes[0] / D;
    const int E = in_sizes[2];

    cudaFuncSetAttribute(precompute_kernel,
                         cudaFuncAttributeMaxDynamicSharedMemorySize, PRE_SMEM_BYTES);
    cudaFuncSetAttribute(edge_kernel,
                         cudaFuncAttributeMaxDynamicSharedMemorySize, EDGE_SMEM_BYTES);

    precompute_kernel<<<148, 256, PRE_SMEM_BYTES>>>(h1, h2, W1, b1, n);
    edge_kernel<<<592, 128, EDGE_SMEM_BYTES>>>(src, dst, W2, b2, W3, b3, out, E, n);
}

// round 13
// speedup vs baseline: 1.0978x; 1.0978x over previous
#include <cuda_runtime.h>
#include <cuda_fp16.h>
#include <cstdint>

#define D 64
#define H 128
#define NMAX 50048

__device__ __align__(16) __half g_P[(size_t)NMAX * H];
__device__ __align__(16) __half g_Q[(size_t)NMAX * H];
__device__ int g_ctr_pre;    // reset by edge_kernel (for next replay)
__device__ int g_ctr_edge;   // reset by precompute_kernel (runs first)

__device__ __forceinline__ float sigt(float x) {
    float t;
    asm("tanh.approx.f32 %0, %1;" : "=f"(t) : "f"(x * 0.5f));
    return fmaf(t, 0.5f, 0.5f);
}
__device__ __forceinline__ uint32_t sigt2u(uint32_t p, uint32_t q) {
    __half2 x = __hadd2(*(__half2*)&p, *(__half2*)&q);
    const __half2 hhalf = __floats2half2_rn(0.5f, 0.5f);
    __half2 xh = __hmul2(x, hhalf);
    uint32_t tu;
    asm("tanh.approx.f16x2 %0, %1;" : "=r"(tu) : "r"(*(uint32_t*)&xh));
    __half2 r = __hfma2(*(__half2*)&tu, hhalf, hhalf);
    return *(uint32_t*)&r;
}
__device__ __forceinline__ uint32_t f16x2(float lo, float hi) {
    __half2 h = __floats2half2_rn(lo, hi);
    return *(uint32_t*)&h;
}

__device__ __forceinline__ void mma_f16(float* c, uint4 a, uint2 b) {
    asm volatile(
        "mma.sync.aligned.m16n8k16.row.col.f32.f16.f16.f32 "
        "{%0,%1,%2,%3}, {%4,%5,%6,%7}, {%8,%9}, {%0,%1,%2,%3};"
        : "+f"(c[0]), "+f"(c[1]), "+f"(c[2]), "+f"(c[3])
        : "r"(a.x), "r"(a.y), "r"(a.z), "r"(a.w), "r"(b.x), "r"(b.y));
}

// Build fp16 A-fragments (m16n8k16 row-major layout, validated R5-R12).
__device__ __forceinline__ void build_frags_h(const float* scr, uint4* A,
                                              int mt_base, int nkt, int t, int nth)
{
    const int ncols = nkt * 16;
    for (int fid = t; fid < 64 * nkt; fid += nth) {
        int fl = fid & 31;
        int kt = (fid >> 5) % nkt;
        int mtl = fid / (32 * nkt);
        int fg = fl >> 2, ft = fl & 3;
        int lr0 = mtl * 16 + fg, lr1 = lr0 + 8;
        int k0 = kt * 16 + ft * 2;
        uint4 hi;
        hi.x = f16x2(scr[lr0 * ncols + k0],     scr[lr0 * ncols + k0 + 1]);
        hi.y = f16x2(scr[lr1 * ncols + k0],     scr[lr1 * ncols + k0 + 1]);
        hi.z = f16x2(scr[lr0 * ncols + k0 + 8], scr[lr0 * ncols + k0 + 9]);
        hi.w = f16x2(scr[lr1 * ncols + k0 + 8], scr[lr1 * ncols + k0 + 9]);
        A[((mt_base + mtl) * nkt + kt) * 32 + fl] = hi;
    }
}

// Legacy staging (precompute): writer XOR = e>>2; reader lane ^ (2*nt+lq).
__device__ __forceinline__ void stage4h(uint32_t* B, int nt, int nn, int xe, int k,
                                        float z0, float z1, float z2, float z3)
{
    uint32_t h01 = f16x2(z0, z1);
    uint32_t h23 = f16x2(z2, z3);
    int kt = k >> 4, kq = (k & 7) >> 1, reg = (k >> 3) & 1;
    int l0 = (nn * 4 + kq) ^ xe, l1 = (nn * 4 + kq + 1) ^ xe;
    int base = (nt * 8 + kt) * 64;
    B[base + l0 * 2 + reg] = h01;
    B[base + l1 * 2 + reg] = h23;
}

// ---------------------------------------------------------------------------
// Precompute (unchanged — ~20us, known good)
// ---------------------------------------------------------------------------
#define P_A1 0
#define P_A2 32768
#define P_B  49152
#define P_B1S 114688
#define PRE_SMEM_BYTES 115712

__global__ void __launch_bounds__(256) precompute_kernel(
    const float* __restrict__ h1, const float* __restrict__ h2,
    const float* __restrict__ W1, const float* __restrict__ b1, int n)
{
    extern __shared__ char smc[];
    uint4* A1 = (uint4*)(smc + P_A1);
    uint4* A2 = (uint4*)(smc + P_A2);
    float* b1s = (float*)(smc + P_B1S);

    const int t = threadIdx.x, lane = t & 31, w = t >> 5;
    const int gid = lane >> 2, tig = lane & 3;

    if (blockIdx.x == 0 && t == 0) g_ctr_edge = 0;

    {
        float* scr = (float*)(smc + P_B);
        for (int chunk = 0; chunk < 4; ++chunk) {
            const int R0 = chunk * 32;
            __syncthreads();
            for (int idx = t; idx < 4096; idx += 256) {
                int r = idx >> 7, k = idx & 127;
                float v;
                if (k < 64) v = W1[(R0 + r) * 256 + k];
                else        v = W1[(R0 + r) * 256 + 64 + k] + W1[(R0 + r) * 256 + 128 + k];
                scr[r * 128 + k] = v;
            }
            __syncthreads();
            build_frags_h(scr, A1, chunk * 2, 8, t, 256);
        }
        for (int chunk = 0; chunk < 4; ++chunk) {
            const int R0 = chunk * 32;
            __syncthreads();
            for (int idx = t; idx < 2048; idx += 256) {
                int r = idx >> 6, k = idx & 63;
                scr[r * 64 + k] = W1[(R0 + r) * 256 + 64 + k];
            }
            __syncthreads();
            build_frags_h(scr, A2, chunk * 2, 4, t, 256);
        }
    }
    if (t < 128) b1s[t] = b1[t];
    __syncthreads();

    float b1r0[8], b1r1[8];
    #pragma unroll
    for (int mt = 0; mt < 8; ++mt) {
        b1r0[mt] = b1s[mt * 16 + gid];
        b1r1[mt] = b1s[mt * 16 + gid + 8];
    }

    uint32_t* Bw = (uint32_t*)(smc + P_B + w * 8192);
    const int e = lane, nt_e = e >> 3, n_e = e & 7, xe = e >> 2;
    const int lq = lane >> 4;
    const int ntiles = (n + 31) >> 5;

    for (;;) {
        int tile;
        if (lane == 0) tile = atomicAdd(&g_ctr_pre, 1);
        tile = __shfl_sync(0xffffffffu, tile, 0);
        if (tile >= ntiles) break;
        const int nb = tile * 32;
        const int node = nb + e;
        __syncwarp();

        if (node < n) {
            const float4* H1 = (const float4*)(h1 + (size_t)node * D);
            const float4* H2 = (const float4*)(h2 + (size_t)node * D);
            #pragma unroll 8
            for (int u = 0; u < 16; ++u) {
                float4 v = H1[u];
                stage4h(Bw, nt_e, n_e, xe, u * 4, v.x, v.y, v.z, v.w);
            }
            #pragma unroll 8
            for (int u = 0; u < 16; ++u) {
                float4 v = H2[u];
                stage4h(Bw, nt_e, n_e, xe, 64 + u * 4, v.x, v.y, v.z, v.w);
            }
        } else {
            #pragma unroll 8
            for (int u = 0; u < 32; ++u)
                stage4h(Bw, nt_e, n_e, xe, u * 4, 0.f, 0.f, 0.f, 0.f);
        }
        __syncwarp();

        float acc[8][4][4];

        #pragma unroll
        for (int mt = 0; mt < 8; ++mt)
            #pragma unroll
            for (int nt = 0; nt < 4; ++nt)
                #pragma unroll
                for (int r = 0; r < 4; ++r) acc[mt][nt][r] = 0.f;

        #pragma unroll 1
        for (int kt = 0; kt < 8; ++kt) {
            uint2 bh[4];
            #pragma unroll
            for (int nt = 0; nt < 4; ++nt)
                bh[nt] = ((const uint2*)Bw)[(nt * 8 + kt) * 32 + (lane ^ (2 * nt + lq))];
            #pragma unroll
            for (int mt = 0; mt < 8; ++mt) {
                uint4 ah = A1[(mt * 8 + kt) * 32 + lane];
                #pragma unroll
                for (int nt = 0; nt < 4; ++nt) mma_f16(acc[mt][nt], ah, bh[nt]);
            }
        }
        #pragma unroll
        for (int nt = 0; nt < 4; ++nt) {
            int n0 = nb + nt * 8 + tig * 2, n1 = n0 + 1;
            #pragma unroll
            for (int mt = 0; mt < 8; ++mt) {
                int r0 = mt * 16 + gid, r1 = r0 + 8;
                if (n0 < n) {
                    g_P[(size_t)n0 * H + r0] = __float2half_rn(acc[mt][nt][0] + b1r0[mt]);
                    g_P[(size_t)n0 * H + r1] = __float2half_rn(acc[mt][nt][2] + b1r1[mt]);
                }
                if (n1 < n) {
                    g_P[(size_t)n1 * H + r0] = __float2half_rn(acc[mt][nt][1] + b1r0[mt]);
                    g_P[(size_t)n1 * H + r1] = __float2half_rn(acc[mt][nt][3] + b1r1[mt]);
                }
            }
        }

        #pragma unroll
        for (int mt = 0; mt < 8; ++mt)
            #pragma unroll
            for (int nt = 0; nt < 4; ++nt)
                #pragma unroll
                for (int r = 0; r < 4; ++r) acc[mt][nt][r] = 0.f;

        #pragma unroll 1
        for (int kt = 0; kt < 4; ++kt) {
            uint2 bh[4];
            #pragma unroll
            for (int nt = 0; nt < 4; ++nt)
                bh[nt] = ((const uint2*)Bw)[(nt * 8 + kt) * 32 + (lane ^ (2 * nt + lq))];
            #pragma unroll
            for (int mt = 0; mt < 8; ++mt) {
                uint4 ah = A2[(mt * 4 + kt) * 32 + lane];
                #pragma unroll
                for (int nt = 0; nt < 4; ++nt) mma_f16(acc[mt][nt], ah, bh[nt]);
            }
        }
        #pragma unroll
        for (int nt = 0; nt < 4; ++nt) {
            int n0 = nb + nt * 8 + tig * 2, n1 = n0 + 1;
            #pragma unroll
            for (int mt = 0; mt < 8; ++mt) {
                int r0 = mt * 16 + gid, r1 = r0 + 8;
                if (n0 < n) {
                    g_Q[(size_t)n0 * H + r0] = __float2half_rn(acc[mt][nt][0]);
                    g_Q[(size_t)n0 * H + r1] = __float2half_rn(acc[mt][nt][2]);
                }
                if (n1 < n) {
                    g_Q[(size_t)n1 * H + r0] = __float2half_rn(acc[mt][nt][1]);
                    g_Q[(size_t)n1 * H + r1] = __float2half_rn(acc[mt][nt][3]);
                }
            }
        }
    }
}

// ---------------------------------------------------------------------------
// Edge kernel: R10 structure + COALESCED warp-cooperative gather.
// Per pass: lanes 0-15 = edge 2p's 16 row-chunks, lanes 16-31 = edge 2p+1's.
// Each LDG.128 touches 4 cache lines (vs 32 before). STS uses ^(kt<<2) word
// swizzle; reader compensates with ^(kt<<1) on its uint2 index.
// ---------------------------------------------------------------------------
#define E_A   0                 // 32 KB
#define E_B   32768             // 8 warps x 8 KB
#define E_B2S 98304
#define E_W3S 98816
#define EDGE_SMEM_BYTES 99840

__global__ void __launch_bounds__(256) edge_kernel(
    const int* __restrict__ src, const int* __restrict__ dst,
    const float* __restrict__ W2, const float* __restrict__ b2,
    const float* __restrict__ W3, const float* __restrict__ b3,
    float* __restrict__ out, int E, int n)
{
    extern __shared__ char smc[];
    uint4* Ahi = (uint4*)(smc + E_A);
    float* b2s = (float*)(smc + E_B2S);
    float* w3s = (float*)(smc + E_W3S);

    const int t = threadIdx.x, lane = t & 31, w = t >> 5;
    const int gid = lane >> 2, tig = lane & 3;

    if (blockIdx.x == 0 && t == 0) g_ctr_pre = 0;

    {
        float* scr = (float*)(smc + E_B);
        for (int chunk = 0; chunk < 4; ++chunk) {
            __syncthreads();
            for (int i = t; i < 1024; i += 256)
                ((float4*)scr)[i] = ((const float4*)W2)[chunk * 1024 + i];
            __syncthreads();
            build_frags_h(scr, Ahi, chunk * 2, 8, t, 256);
        }
    }
    if (t < 128) { b2s[t] = b2[t]; w3s[t] = W3[t]; }
    __syncthreads();

    float b2r0[8], b2r1[8], w3r0[8], w3r1[8];
    #pragma unroll
    for (int mt = 0; mt < 8; ++mt) {
        b2r0[mt] = b2s[mt * 16 + gid];
        b2r1[mt] = b2s[mt * 16 + gid + 8];
        w3r0[mt] = w3s[mt * 16 + gid];
        w3r1[mt] = w3s[mt * 16 + gid + 8];
    }
    const float b3v = b3[0];

    uint32_t* Bw = (uint32_t*)(smc + E_B + w * 8192);
    const int lq = lane >> 4;
    const int chunk = lane & 15, half = lane >> 4;  // gather role
    const int kt_l = chunk >> 1, reg_l = chunk & 1; // this lane's (kt, reg)
    const int ntiles = (E + 31) >> 5;

    for (;;) {
        int tile;
        if (lane == 0) tile = atomicAdd(&g_ctr_edge, 1);
        tile = __shfl_sync(0xffffffffu, tile, 0);
        if (tile >= ntiles) break;
        const int e0 = tile * 32;

        // preload this lane's edge indices (lane = edge within tile);
        // OOB edges read node 0 (finite junk; columns discarded at output)
        int sA = 0, dA = 0;
        {
            int gl = e0 + lane;
            if (gl < E) {
                sA = min(max(src[gl], 0), n - 1);
                dA = min(max(dst[gl], 0), n - 1);
            }
        }
        __syncwarp();

        // coalesced staging: 16 passes x 2 edges
        #pragma unroll 4
        for (int p = 0; p < 16; ++p) {
            int eo = 2 * p + half;
            int s = __shfl_sync(0xffffffffu, sA, eo);
            int d = __shfl_sync(0xffffffffu, dA, eo);
            uint4 pv = *(const uint4*)(g_P + (size_t)s * H + chunk * 8);
            uint4 qv = *(const uint4*)(g_Q + (size_t)d * H + chunk * 8);
            uint32_t w0 = sigt2u(pv.x, qv.x);   // k = chunk*8 + {0,1}
            uint32_t w1 = sigt2u(pv.y, qv.y);   // + {2,3}
            uint32_t w2 = sigt2u(pv.z, qv.z);   // + {4,5}
            uint32_t w3v_ = sigt2u(pv.w, qv.w); // + {6,7}
            int nt = eo >> 3, nn = eo & 7, xe = eo >> 2;
            uint32_t* slab = Bw + (nt * 8 + kt_l) * 64;
            int wx = kt_l << 2;
            slab[(((((nn * 4 + 0) ^ xe) << 1) + reg_l) ^ wx)] = w0;
            slab[(((((nn * 4 + 1) ^ xe) << 1) + reg_l) ^ wx)] = w1;
            slab[(((((nn * 4 + 2) ^ xe) << 1) + reg_l) ^ wx)] = w2;
            slab[(((((nn * 4 + 3) ^ xe) << 1) + reg_l) ^ wx)] = w3v_;
        }
        __syncwarp();

        float acc[8][4][4];
        #pragma unroll
        for (int mt = 0; mt < 8; ++mt)
            #pragma unroll
            for (int nt = 0; nt < 4; ++nt)
                #pragma unroll
                for (int r = 0; r < 4; ++r) acc[mt][nt][r] = 0.f;

        #pragma unroll 1
        for (int kt = 0; kt < 8; ++kt) {
            uint2 bh[4];
            #pragma unroll
            for (int nt = 0; nt < 4; ++nt)
                bh[nt] = ((const uint2*)Bw)[(nt * 8 + kt) * 32 +
                                            ((lane ^ (2 * nt + lq)) ^ (kt << 1))];
            #pragma unroll
            for (int mt = 0; mt < 8; ++mt) {
                uint4 ah = Ahi[(mt * 8 + kt) * 32 + lane];
                #pragma unroll
                for (int nt = 0; nt < 4; ++nt) mma_f16(acc[mt][nt], ah, bh[nt]);
            }
        }

        // epilogue (fp32 sigt; reduce over gid lanes)
        #pragma unroll
        for (int nt = 0; nt < 4; ++nt) {
            float s0 = 0.f, s1 = 0.f;
            #pragma unroll
            for (int mt = 0; mt < 8; ++mt) {
                s0 += sigt(acc[mt][nt][0] + b2r0[mt]) * w3r0[mt]
                    + sigt(acc[mt][nt][2] + b2r1[mt]) * w3r1[mt];
                s1 += sigt(acc[mt][nt][1] + b2r0[mt]) * w3r0[mt]
                    + sigt(acc[mt][nt][3] + b2r1[mt]) * w3r1[mt];
            }
            #pragma unroll
            for (int off = 4; off <= 16; off <<= 1) {
                s0 += __shfl_xor_sync(0xffffffffu, s0, off);
                s1 += __shfl_xor_sync(0xffffffffu, s1, off);
            }
            if (gid == 0) {
                int go = e0 + nt * 8 + tig * 2;
                if (go + 1 < E)
                    *(float2*)(out + go) = make_float2(s0 + b3v, s1 + b3v);
                else if (go < E)
                    out[go] = s0 + b3v;
            }
        }
    }
}

extern "C" void kernel_launch(void* const* d_in, const int* in_sizes, int n_in,
                              void* d_out, int out_size)
{
    const float* h1 = (const float*)d_in[0];
    const float* h2 = (const float*)d_in[1];
    const int* src = (const int*)d_in[2];
    const int* dst = (const int*)d_in[3];
    const float* W1 = (const float*)d_in[4];
    const float* b1 = (const float*)d_in[5];
    const float* W2 = (const float*)d_in[6];
    const float* b2 = (const float*)d_in[7];
    const float* W3 = (const float*)d_in[8];
    const float* b3 = (const float*)d_in[9];
    float* out = (float*)d_out;

    const int n = in_sizes[0] / D;
    const int E = in_sizes[2];

    cudaFuncSetAttribute(precompute_kernel,
                         cudaFuncAttributeMaxDynamicSharedMemorySize, PRE_SMEM_BYTES);
    cudaFuncSetAttribute(edge_kernel,
                         cudaFuncAttributeMaxDynamicSharedMemorySize, EDGE_SMEM_BYTES);

    precompute_kernel<<<148, 256, PRE_SMEM_BYTES>>>(h1, h2, W1, b1, n);
    edge_kernel<<<148, 256, EDGE_SMEM_BYTES>>>(src, dst, W2, b2, W3, b3, out, E, n);
}

// round 14
// speedup vs baseline: 1.2926x; 1.1775x over previous
#include <cuda_runtime.h>
#include <cuda_fp16.h>
#include <cstdint>

#define D 64
#define H 128
#define NMAX 50048

__device__ __align__(16) __half g_P[(size_t)NMAX * H];
__device__ __align__(16) __half g_Q[(size_t)NMAX * H];
__device__ int g_ctr_pre;    // reset by edge_kernel (for next replay)
__device__ int g_ctr_edge;   // reset by precompute_kernel (runs first)

__device__ __forceinline__ float sigt(float x) {
    float t;
    asm("tanh.approx.f32 %0, %1;" : "=f"(t) : "f"(x * 0.5f));
    return fmaf(t, 0.5f, 0.5f);
}
__device__ __forceinline__ uint32_t sigt2u(uint32_t p, uint32_t q) {
    __half2 x = __hadd2(*(__half2*)&p, *(__half2*)&q);
    const __half2 hhalf = __floats2half2_rn(0.5f, 0.5f);
    __half2 xh = __hmul2(x, hhalf);
    uint32_t tu;
    asm("tanh.approx.f16x2 %0, %1;" : "=r"(tu) : "r"(*(uint32_t*)&xh));
    __half2 r = __hfma2(*(__half2*)&tu, hhalf, hhalf);
    return *(uint32_t*)&r;
}
__device__ __forceinline__ uint32_t f16x2(float lo, float hi) {
    __half2 h = __floats2half2_rn(lo, hi);
    return *(uint32_t*)&h;
}
__device__ __forceinline__ float2 h2f2u(uint32_t u) {
    return __half22float2(*(__half2*)&u);
}

// fp32-acc MMA (precompute — P/Q accuracy matters)
__device__ __forceinline__ void mma_f16(float* c, uint4 a, uint2 b) {
    asm volatile(
        "mma.sync.aligned.m16n8k16.row.col.f32.f16.f16.f32 "
        "{%0,%1,%2,%3}, {%4,%5,%6,%7}, {%8,%9}, {%0,%1,%2,%3};"
        : "+f"(c[0]), "+f"(c[1]), "+f"(c[2]), "+f"(c[3])
        : "r"(a.x), "r"(a.y), "r"(a.z), "r"(a.w), "r"(b.x), "r"(b.y));
}
// fp16-acc MMA (edge layer-2 — halves accumulator registers)
__device__ __forceinline__ void mma_f16acc(uint32_t* c, uint4 a, uint2 b) {
    asm volatile(
        "mma.sync.aligned.m16n8k16.row.col.f16.f16.f16.f16 "
        "{%0,%1}, {%2,%3,%4,%5}, {%6,%7}, {%0,%1};"
        : "+r"(c[0]), "+r"(c[1])
        : "r"(a.x), "r"(a.y), "r"(a.z), "r"(a.w), "r"(b.x), "r"(b.y));
}

// Build fp16 A-fragments (m16n8k16 row-major layout, validated R5-R13).
__device__ __forceinline__ void build_frags_h(const float* scr, uint4* A,
                                              int mt_base, int nkt, int t, int nth)
{
    const int ncols = nkt * 16;
    for (int fid = t; fid < 64 * nkt; fid += nth) {
        int fl = fid & 31;
        int kt = (fid >> 5) % nkt;
        int mtl = fid / (32 * nkt);
        int fg = fl >> 2, ft = fl & 3;
        int lr0 = mtl * 16 + fg, lr1 = lr0 + 8;
        int k0 = kt * 16 + ft * 2;
        uint4 hi;
        hi.x = f16x2(scr[lr0 * ncols + k0],     scr[lr0 * ncols + k0 + 1]);
        hi.y = f16x2(scr[lr1 * ncols + k0],     scr[lr1 * ncols + k0 + 1]);
        hi.z = f16x2(scr[lr0 * ncols + k0 + 8], scr[lr0 * ncols + k0 + 9]);
        hi.w = f16x2(scr[lr1 * ncols + k0 + 8], scr[lr1 * ncols + k0 + 9]);
        A[((mt_base + mtl) * nkt + kt) * 32 + fl] = hi;
    }
}

// Coalesced staging store (R13-validated): 2 packed words for k..k+3 (k%4==0)
// of fragment-column nn, group nt. Word-index swizzle ^= kt<<2; readers
// compensate with ^(kt<<1) on their uint2 index.
__device__ __forceinline__ void stage4x(uint32_t* Bw, int nt, int nn, int xe,
                                        int k, uint32_t w01, uint32_t w23)
{
    int kt = k >> 4, kq = (k & 7) >> 1, reg = (k >> 3) & 1, wx = kt << 2;
    uint32_t* slab = Bw + (nt * 8 + kt) * 64;
    slab[((((nn * 4 + kq) ^ xe) << 1) + reg) ^ wx] = w01;
    slab[((((nn * 4 + kq + 1) ^ xe) << 1) + reg) ^ wx] = w23;
}

// ---------------------------------------------------------------------------
// Precompute: P[n] = b1 + [Wa | Wc+Wd] @ [h1;h2],  Q[n] = Wb @ h1  (fp16 out)
// 256 threads, 8 independent warps. Coalesced staging (node rows contiguous).
// ---------------------------------------------------------------------------
#define P_A1 0
#define P_A2 32768
#define P_B  49152
#define P_B1S 114688
#define PRE_SMEM_BYTES 115712

__global__ void __launch_bounds__(256) precompute_kernel(
    const float* __restrict__ h1, const float* __restrict__ h2,
    const float* __restrict__ W1, const float* __restrict__ b1, int n)
{
    extern __shared__ char smc[];
    uint4* A1 = (uint4*)(smc + P_A1);
    uint4* A2 = (uint4*)(smc + P_A2);
    float* b1s = (float*)(smc + P_B1S);

    const int t = threadIdx.x, lane = t & 31, w = t >> 5;
    const int gid = lane >> 2, tig = lane & 3;

    if (blockIdx.x == 0 && t == 0) g_ctr_edge = 0;

    {
        float* scr = (float*)(smc + P_B);
        for (int chunk = 0; chunk < 4; ++chunk) {
            const int R0 = chunk * 32;
            __syncthreads();
            for (int idx = t; idx < 4096; idx += 256) {
                int r = idx >> 7, k = idx & 127;
                float v;
                if (k < 64) v = W1[(R0 + r) * 256 + k];
                else        v = W1[(R0 + r) * 256 + 64 + k] + W1[(R0 + r) * 256 + 128 + k];
                scr[r * 128 + k] = v;
            }
            __syncthreads();
            build_frags_h(scr, A1, chunk * 2, 8, t, 256);
        }
        for (int chunk = 0; chunk < 4; ++chunk) {
            const int R0 = chunk * 32;
            __syncthreads();
            for (int idx = t; idx < 2048; idx += 256) {
                int r = idx >> 6, k = idx & 63;
                scr[r * 64 + k] = W1[(R0 + r) * 256 + 64 + k];
            }
            __syncthreads();
            build_frags_h(scr, A2, chunk * 2, 4, t, 256);
        }
    }
    if (t < 128) b1s[t] = b1[t];
    __syncthreads();

    float b1r0[8], b1r1[8];
    #pragma unroll
    for (int mt = 0; mt < 8; ++mt) {
        b1r0[mt] = b1s[mt * 16 + gid];
        b1r1[mt] = b1s[mt * 16 + gid + 8];
    }

    uint32_t* Bw = (uint32_t*)(smc + P_B + w * 8192);
    const int lq = lane >> 4;
    const int chunk = lane & 15, half = lane >> 4;
    const int ntiles = (n + 31) >> 5;

    for (;;) {
        int tile;
        if (lane == 0) tile = atomicAdd(&g_ctr_pre, 1);
        tile = __shfl_sync(0xffffffffu, tile, 0);
        if (tile >= ntiles) break;
        const int nb = tile * 32;
        __syncwarp();

        // coalesced staging: pass p covers nodes nb+2p, nb+2p+1 (contiguous rows)
        #pragma unroll 4
        for (int p = 0; p < 16; ++p) {
            int eo = 2 * p + half;
            int node = nb + eo;
            int nt = eo >> 3, nn = eo & 7, xe = eo >> 2;
            float4 v1 = make_float4(0.f, 0.f, 0.f, 0.f), v2 = v1;
            if (node < n) {
                v1 = *(const float4*)(h1 + (size_t)node * D + chunk * 4);
                v2 = *(const float4*)(h2 + (size_t)node * D + chunk * 4);
            }
            stage4x(Bw, nt, nn, xe, chunk * 4,      f16x2(v1.x, v1.y), f16x2(v1.z, v1.w));
            stage4x(Bw, nt, nn, xe, 64 + chunk * 4, f16x2(v2.x, v2.y), f16x2(v2.z, v2.w));
        }
        __syncwarp();

        float acc[8][4][4];

        // ---- P pass: A1, K=128
        #pragma unroll
        for (int mt = 0; mt < 8; ++mt)
            #pragma unroll
            for (int nt = 0; nt < 4; ++nt)
                #pragma unroll
                for (int r = 0; r < 4; ++r) acc[mt][nt][r] = 0.f;

        #pragma unroll 1
        for (int kt = 0; kt < 8; ++kt) {
            uint2 bh[4];
            #pragma unroll
            for (int nt = 0; nt < 4; ++nt)
                bh[nt] = ((const uint2*)Bw)[(nt * 8 + kt) * 32 +
                                            ((lane ^ (2 * nt + lq)) ^ (kt << 1))];
            #pragma unroll
            for (int mt = 0; mt < 8; ++mt) {
                uint4 ah = A1[(mt * 8 + kt) * 32 + lane];
                #pragma unroll
                for (int nt = 0; nt < 4; ++nt) mma_f16(acc[mt][nt], ah, bh[nt]);
            }
        }
        #pragma unroll
        for (int nt = 0; nt < 4; ++nt) {
            int n0 = nb + nt * 8 + tig * 2, n1 = n0 + 1;
            #pragma unroll
            for (int mt = 0; mt < 8; ++mt) {
                int r0 = mt * 16 + gid, r1 = r0 + 8;
                if (n0 < n) {
                    g_P[(size_t)n0 * H + r0] = __float2half_rn(acc[mt][nt][0] + b1r0[mt]);
                    g_P[(size_t)n0 * H + r1] = __float2half_rn(acc[mt][nt][2] + b1r1[mt]);
                }
                if (n1 < n) {
                    g_P[(size_t)n1 * H + r0] = __float2half_rn(acc[mt][nt][1] + b1r0[mt]);
                    g_P[(size_t)n1 * H + r1] = __float2half_rn(acc[mt][nt][3] + b1r1[mt]);
                }
            }
        }

        // ---- Q pass: A2, K=64 (B slabs kt 0..3 hold h1)
        #pragma unroll
        for (int mt = 0; mt < 8; ++mt)
            #pragma unroll
            for (int nt = 0; nt < 4; ++nt)
                #pragma unroll
                for (int r = 0; r < 4; ++r) acc[mt][nt][r] = 0.f;

        #pragma unroll 1
        for (int kt = 0; kt < 4; ++kt) {
            uint2 bh[4];
            #pragma unroll
            for (int nt = 0; nt < 4; ++nt)
                bh[nt] = ((const uint2*)Bw)[(nt * 8 + kt) * 32 +
                                            ((lane ^ (2 * nt + lq)) ^ (kt << 1))];
            #pragma unroll
            for (int mt = 0; mt < 8; ++mt) {
                uint4 ah = A2[(mt * 4 + kt) * 32 + lane];
                #pragma unroll
                for (int nt = 0; nt < 4; ++nt) mma_f16(acc[mt][nt], ah, bh[nt]);
            }
        }
        #pragma unroll
        for (int nt = 0; nt < 4; ++nt) {
            int n0 = nb + nt * 8 + tig * 2, n1 = n0 + 1;
            #pragma unroll
            for (int mt = 0; mt < 8; ++mt) {
                int r0 = mt * 16 + gid, r1 = r0 + 8;
                if (n0 < n) {
                    g_Q[(size_t)n0 * H + r0] = __float2half_rn(acc[mt][nt][0]);
                    g_Q[(size_t)n0 * H + r1] = __float2half_rn(acc[mt][nt][2]);
                }
                if (n1 < n) {
                    g_Q[(size_t)n1 * H + r0] = __float2half_rn(acc[mt][nt][1]);
                    g_Q[(size_t)n1 * H + r1] = __float2half_rn(acc[mt][nt][3]);
                }
            }
        }
    }
}

// ---------------------------------------------------------------------------
// Edge kernel: R13 coalesced gather + fp16 accumulators (64 acc regs).
// 128-thread blocks, independent warps, natural regs -> 3 blocks/SM.
// ---------------------------------------------------------------------------
#define E_A   0                 // 32 KB
#define E_B   32768             // 4 warps x 8 KB
#define E_B2S 65536
#define E_W3S 66048
#define EDGE_SMEM_BYTES 66560

__global__ void __launch_bounds__(128) edge_kernel(
    const int* __restrict__ src, const int* __restrict__ dst,
    const float* __restrict__ W2, const float* __restrict__ b2,
    const float* __restrict__ W3, const float* __restrict__ b3,
    float* __restrict__ out, int E, int n)
{
    extern __shared__ char smc[];
    uint4* Ahi = (uint4*)(smc + E_A);
    float* b2s = (float*)(smc + E_B2S);
    float* w3s = (float*)(smc + E_W3S);

    const int t = threadIdx.x, lane = t & 31, w = t >> 5;
    const int gid = lane >> 2, tig = lane & 3;

    if (blockIdx.x == 0 && t == 0) g_ctr_pre = 0;

    {
        float* scr = (float*)(smc + E_B);
        for (int chunk = 0; chunk < 4; ++chunk) {
            __syncthreads();
            for (int i = t; i < 1024; i += 128)
                ((float4*)scr)[i] = ((const float4*)W2)[chunk * 1024 + i];
            __syncthreads();
            build_frags_h(scr, Ahi, chunk * 2, 8, t, 128);
        }
    }
    b2s[t] = b2[t];
    w3s[t] = W3[t];
    __syncthreads();

    float b2r0[8], b2r1[8], w3r0[8], w3r1[8];
    #pragma unroll
    for (int mt = 0; mt < 8; ++mt) {
        b2r0[mt] = b2s[mt * 16 + gid];
        b2r1[mt] = b2s[mt * 16 + gid + 8];
        w3r0[mt] = w3s[mt * 16 + gid];
        w3r1[mt] = w3s[mt * 16 + gid + 8];
    }
    const float b3v = b3[0];

    uint32_t* Bw = (uint32_t*)(smc + E_B + w * 8192);
    const int lq = lane >> 4;
    const int chunk = lane & 15, half = lane >> 4;
    const int ntiles = (E + 31) >> 5;

    for (;;) {
        int tile;
        if (lane == 0) tile = atomicAdd(&g_ctr_edge, 1);
        tile = __shfl_sync(0xffffffffu, tile, 0);
        if (tile >= ntiles) break;
        const int e0 = tile * 32;

        // preload this lane's edge indices (lane = edge within tile);
        // OOB edges read node 0 (finite junk; columns discarded at output)
        int sA = 0, dA = 0;
        {
            int gl = e0 + lane;
            if (gl < E) {
                sA = min(max(src[gl], 0), n - 1);
                dA = min(max(dst[gl], 0), n - 1);
            }
        }
        __syncwarp();

        // coalesced staging: 16 passes x 2 edges (4 lines per LDG.128)
        #pragma unroll 4
        for (int p = 0; p < 16; ++p) {
            int eo = 2 * p + half;
            int s = __shfl_sync(0xffffffffu, sA, eo);
            int d = __shfl_sync(0xffffffffu, dA, eo);
            uint4 pv = *(const uint4*)(g_P + (size_t)s * H + chunk * 8);
            uint4 qv = *(const uint4*)(g_Q + (size_t)d * H + chunk * 8);
            int nt = eo >> 3, nn = eo & 7, xe = eo >> 2;
            stage4x(Bw, nt, nn, xe, chunk * 8,
                    sigt2u(pv.x, qv.x), sigt2u(pv.y, qv.y));
            stage4x(Bw, nt, nn, xe, chunk * 8 + 4,
                    sigt2u(pv.z, qv.z), sigt2u(pv.w, qv.w));
        }
        __syncwarp();

        // MMA mainloop, fp16 accumulators (packed pairs)
        uint32_t acc[8][4][2];
        #pragma unroll
        for (int mt = 0; mt < 8; ++mt)
            #pragma unroll
            for (int nt = 0; nt < 4; ++nt) { acc[mt][nt][0] = 0u; acc[mt][nt][1] = 0u; }

        #pragma unroll 1
        for (int kt = 0; kt < 8; ++kt) {
            uint2 bh[4];
            #pragma unroll
            for (int nt = 0; nt < 4; ++nt)
                bh[nt] = ((const uint2*)Bw)[(nt * 8 + kt) * 32 +
                                            ((lane ^ (2 * nt + lq)) ^ (kt << 1))];
            #pragma unroll
            for (int mt = 0; mt < 8; ++mt) {
                uint4 ah = Ahi[(mt * 8 + kt) * 32 + lane];
                #pragma unroll
                for (int nt = 0; nt < 4; ++nt) mma_f16acc(acc[mt][nt], ah, bh[nt]);
            }
        }

        // epilogue (fp32 sigt; acc reg0 = rows gid, reg1 = rows gid+8,
        // halves = cols 2tig, 2tig+1)
        #pragma unroll
        for (int nt = 0; nt < 4; ++nt) {
            float s0 = 0.f, s1 = 0.f;
            #pragma unroll
            for (int mt = 0; mt < 8; ++mt) {
                float2 lo = h2f2u(acc[mt][nt][0]);
                float2 hi = h2f2u(acc[mt][nt][1]);
                s0 += sigt(lo.x + b2r0[mt]) * w3r0[mt]
                    + sigt(hi.x + b2r1[mt]) * w3r1[mt];
                s1 += sigt(lo.y + b2r0[mt]) * w3r0[mt]
                    + sigt(hi.y + b2r1[mt]) * w3r1[mt];
            }
            #pragma unroll
            for (int off = 4; off <= 16; off <<= 1) {
                s0 += __shfl_xor_sync(0xffffffffu, s0, off);
                s1 += __shfl_xor_sync(0xffffffffu, s1, off);
            }
            if (gid == 0) {
                int go = e0 + nt * 8 + tig * 2;
                if (go + 1 < E)
                    *(float2*)(out + go) = make_float2(s0 + b3v, s1 + b3v);
                else if (go < E)
                    out[go] = s0 + b3v;
            }
        }
    }
}

extern "C" void kernel_launch(void* const* d_in, const int* in_sizes, int n_in,
                              void* d_out, int out_size)
{
    const float* h1 = (const float*)d_in[0];
    const float* h2 = (const float*)d_in[1];
    const int* src = (const int*)d_in[2];
    const int* dst = (const int*)d_in[3];
    const float* W1 = (const float*)d_in[4];
    const float* b1 = (const float*)d_in[5];
    const float* W2 = (const float*)d_in[6];
    const float* b2 = (const float*)d_in[7];
    const float* W3 = (const float*)d_in[8];
    const float* b3 = (const float*)d_in[9];
    float* out = (float*)d_out;

    const int n = in_sizes[0] / D;
    const int E = in_sizes[2];

    cudaFuncSetAttribute(precompute_kernel,
                         cudaFuncAttributeMaxDynamicSharedMemorySize, PRE_SMEM_BYTES);
    cudaFuncSetAttribute(edge_kernel,
                         cudaFuncAttributeMaxDynamicSharedMemorySize, EDGE_SMEM_BYTES);

    precompute_kernel<<<148, 256, PRE_SMEM_BYTES>>>(h1, h2, W1, b1, n);
    edge_kernel<<<444, 128, EDGE_SMEM_BYTES>>>(src, dst, W2, b2, W3, b3, out, E, n);
}

// round 15
// speedup vs baseline: 1.3541x; 1.0476x over previous
#include <cuda_runtime.h>
#include <cuda_fp16.h>
#include <cstdint>

#define D 64
#define H 128
#define NMAX 50048

__device__ __align__(16) __half g_P[(size_t)NMAX * H];
__device__ __align__(16) __half g_Q[(size_t)NMAX * H];
__device__ int g_ctr_pre;    // reset by edge_kernel (for next replay)
__device__ int g_ctr_edge;   // reset by precompute_kernel (runs first)

__device__ __forceinline__ float sigt(float x) {
    float t;
    asm("tanh.approx.f32 %0, %1;" : "=f"(t) : "f"(x * 0.5f));
    return fmaf(t, 0.5f, 0.5f);
}
__device__ __forceinline__ uint32_t sigt2u(uint32_t p, uint32_t q) {
    __half2 x = __hadd2(*(__half2*)&p, *(__half2*)&q);
    const __half2 hhalf = __floats2half2_rn(0.5f, 0.5f);
    __half2 xh = __hmul2(x, hhalf);
    uint32_t tu;
    asm("tanh.approx.f16x2 %0, %1;" : "=r"(tu) : "r"(*(uint32_t*)&xh));
    __half2 r = __hfma2(*(__half2*)&tu, hhalf, hhalf);
    return *(uint32_t*)&r;
}
__device__ __forceinline__ uint32_t f16x2(float lo, float hi) {
    __half2 h = __floats2half2_rn(lo, hi);
    return *(uint32_t*)&h;
}
__device__ __forceinline__ float2 h2f2u(uint32_t u) {
    return __half22float2(*(__half2*)&u);
}

// fp32-acc MMA (precompute — P/Q accuracy matters)
__device__ __forceinline__ void mma_f16(float* c, uint4 a, uint2 b) {
    asm volatile(
        "mma.sync.aligned.m16n8k16.row.col.f32.f16.f16.f32 "
        "{%0,%1,%2,%3}, {%4,%5,%6,%7}, {%8,%9}, {%0,%1,%2,%3};"
        : "+f"(c[0]), "+f"(c[1]), "+f"(c[2]), "+f"(c[3])
        : "r"(a.x), "r"(a.y), "r"(a.z), "r"(a.w), "r"(b.x), "r"(b.y));
}
// fp16-acc MMA (edge layer-2 — halves accumulator registers; R14 win)
__device__ __forceinline__ void mma_f16acc(uint32_t* c, uint4 a, uint2 b) {
    asm volatile(
        "mma.sync.aligned.m16n8k16.row.col.f16.f16.f16.f16 "
        "{%0,%1}, {%2,%3,%4,%5}, {%6,%7}, {%0,%1};"
        : "+r"(c[0]), "+r"(c[1])
        : "r"(a.x), "r"(a.y), "r"(a.z), "r"(a.w), "r"(b.x), "r"(b.y));
}

// Build fp16 A-fragments (m16n8k16 row-major layout, validated R5-R14).
__device__ __forceinline__ void build_frags_h(const float* scr, uint4* A,
                                              int mt_base, int nkt, int t, int nth)
{
    const int ncols = nkt * 16;
    for (int fid = t; fid < 64 * nkt; fid += nth) {
        int fl = fid & 31;
        int kt = (fid >> 5) % nkt;
        int mtl = fid / (32 * nkt);
        int fg = fl >> 2, ft = fl & 3;
        int lr0 = mtl * 16 + fg, lr1 = lr0 + 8;
        int k0 = kt * 16 + ft * 2;
        uint4 hi;
        hi.x = f16x2(scr[lr0 * ncols + k0],     scr[lr0 * ncols + k0 + 1]);
        hi.y = f16x2(scr[lr1 * ncols + k0],     scr[lr1 * ncols + k0 + 1]);
        hi.z = f16x2(scr[lr0 * ncols + k0 + 8], scr[lr0 * ncols + k0 + 9]);
        hi.w = f16x2(scr[lr1 * ncols + k0 + 8], scr[lr1 * ncols + k0 + 9]);
        A[((mt_base + mtl) * nkt + kt) * 32 + fl] = hi;
    }
}

// Legacy staging (precompute, R13-proven): writer XOR = e>>2; reader
// lane ^ (2*nt+lq), no kt word-swizzle.
__device__ __forceinline__ void stage4h(uint32_t* B, int nt, int nn, int xe, int k,
                                        float z0, float z1, float z2, float z3)
{
    uint32_t h01 = f16x2(z0, z1);
    uint32_t h23 = f16x2(z2, z3);
    int kt = k >> 4, kq = (k & 7) >> 1, reg = (k >> 3) & 1;
    int l0 = (nn * 4 + kq) ^ xe, l1 = (nn * 4 + kq + 1) ^ xe;
    int base = (nt * 8 + kt) * 64;
    B[base + l0 * 2 + reg] = h01;
    B[base + l1 * 2 + reg] = h23;
}

// Coalesced staging store (edge, R13/R14-validated): word swizzle ^(kt<<2);
// readers compensate with ^(kt<<1) on their uint2 index.
__device__ __forceinline__ void stage4x(uint32_t* Bw, int nt, int nn, int xe,
                                        int k, uint32_t w01, uint32_t w23)
{
    int kt = k >> 4, kq = (k & 7) >> 1, reg = (k >> 3) & 1, wx = kt << 2;
    uint32_t* slab = Bw + (nt * 8 + kt) * 64;
    slab[((((nn * 4 + kq) ^ xe) << 1) + reg) ^ wx] = w01;
    slab[((((nn * 4 + kq + 1) ^ xe) << 1) + reg) ^ wx] = w23;
}

// ---------------------------------------------------------------------------
// Precompute (R13 version verbatim — measured 20.3us; R14's port regressed it)
// ---------------------------------------------------------------------------
#define P_A1 0
#define P_A2 32768
#define P_B  49152
#define P_B1S 114688
#define PRE_SMEM_BYTES 115712

__global__ void __launch_bounds__(256) precompute_kernel(
    const float* __restrict__ h1, const float* __restrict__ h2,
    const float* __restrict__ W1, const float* __restrict__ b1, int n)
{
    extern __shared__ char smc[];
    uint4* A1 = (uint4*)(smc + P_A1);
    uint4* A2 = (uint4*)(smc + P_A2);
    float* b1s = (float*)(smc + P_B1S);

    const int t = threadIdx.x, lane = t & 31, w = t >> 5;
    const int gid = lane >> 2, tig = lane & 3;

    if (blockIdx.x == 0 && t == 0) g_ctr_edge = 0;

    {
        float* scr = (float*)(smc + P_B);
        for (int chunk = 0; chunk < 4; ++chunk) {
            const int R0 = chunk * 32;
            __syncthreads();
            for (int idx = t; idx < 4096; idx += 256) {
                int r = idx >> 7, k = idx & 127;
                float v;
                if (k < 64) v = W1[(R0 + r) * 256 + k];
                else        v = W1[(R0 + r) * 256 + 64 + k] + W1[(R0 + r) * 256 + 128 + k];
                scr[r * 128 + k] = v;
            }
            __syncthreads();
            build_frags_h(scr, A1, chunk * 2, 8, t, 256);
        }
        for (int chunk = 0; chunk < 4; ++chunk) {
            const int R0 = chunk * 32;
            __syncthreads();
            for (int idx = t; idx < 2048; idx += 256) {
                int r = idx >> 6, k = idx & 63;
                scr[r * 64 + k] = W1[(R0 + r) * 256 + 64 + k];
            }
            __syncthreads();
            build_frags_h(scr, A2, chunk * 2, 4, t, 256);
        }
    }
    if (t < 128) b1s[t] = b1[t];
    __syncthreads();

    float b1r0[8], b1r1[8];
    #pragma unroll
    for (int mt = 0; mt < 8; ++mt) {
        b1r0[mt] = b1s[mt * 16 + gid];
        b1r1[mt] = b1s[mt * 16 + gid + 8];
    }

    uint32_t* Bw = (uint32_t*)(smc + P_B + w * 8192);
    const int e = lane, nt_e = e >> 3, n_e = e & 7, xe = e >> 2;
    const int lq = lane >> 4;
    const int ntiles = (n + 31) >> 5;

    for (;;) {
        int tile;
        if (lane == 0) tile = atomicAdd(&g_ctr_pre, 1);
        tile = __shfl_sync(0xffffffffu, tile, 0);
        if (tile >= ntiles) break;
        const int nb = tile * 32;
        const int node = nb + e;
        __syncwarp();

        if (node < n) {
            const float4* H1 = (const float4*)(h1 + (size_t)node * D);
            const float4* H2 = (const float4*)(h2 + (size_t)node * D);
            #pragma unroll 8
            for (int u = 0; u < 16; ++u) {
                float4 v = H1[u];
                stage4h(Bw, nt_e, n_e, xe, u * 4, v.x, v.y, v.z, v.w);
            }
            #pragma unroll 8
            for (int u = 0; u < 16; ++u) {
                float4 v = H2[u];
                stage4h(Bw, nt_e, n_e, xe, 64 + u * 4, v.x, v.y, v.z, v.w);
            }
        } else {
            #pragma unroll 8
            for (int u = 0; u < 32; ++u)
                stage4h(Bw, nt_e, n_e, xe, u * 4, 0.f, 0.f, 0.f, 0.f);
        }
        __syncwarp();

        float acc[8][4][4];

        #pragma unroll
        for (int mt = 0; mt < 8; ++mt)
            #pragma unroll
            for (int nt = 0; nt < 4; ++nt)
                #pragma unroll
                for (int r = 0; r < 4; ++r) acc[mt][nt][r] = 0.f;

        #pragma unroll 1
        for (int kt = 0; kt < 8; ++kt) {
            uint2 bh[4];
            #pragma unroll
            for (int nt = 0; nt < 4; ++nt)
                bh[nt] = ((const uint2*)Bw)[(nt * 8 + kt) * 32 + (lane ^ (2 * nt + lq))];
            #pragma unroll
            for (int mt = 0; mt < 8; ++mt) {
                uint4 ah = A1[(mt * 8 + kt) * 32 + lane];
                #pragma unroll
                for (int nt = 0; nt < 4; ++nt) mma_f16(acc[mt][nt], ah, bh[nt]);
            }
        }
        #pragma unroll
        for (int nt = 0; nt < 4; ++nt) {
            int n0 = nb + nt * 8 + tig * 2, n1 = n0 + 1;
            #pragma unroll
            for (int mt = 0; mt < 8; ++mt) {
                int r0 = mt * 16 + gid, r1 = r0 + 8;
                if (n0 < n) {
                    g_P[(size_t)n0 * H + r0] = __float2half_rn(acc[mt][nt][0] + b1r0[mt]);
                    g_P[(size_t)n0 * H + r1] = __float2half_rn(acc[mt][nt][2] + b1r1[mt]);
                }
                if (n1 < n) {
                    g_P[(size_t)n1 * H + r0] = __float2half_rn(acc[mt][nt][1] + b1r0[mt]);
                    g_P[(size_t)n1 * H + r1] = __float2half_rn(acc[mt][nt][3] + b1r1[mt]);
                }
            }
        }

        #pragma unroll
        for (int mt = 0; mt < 8; ++mt)
            #pragma unroll
            for (int nt = 0; nt < 4; ++nt)
                #pragma unroll
                for (int r = 0; r < 4; ++r) acc[mt][nt][r] = 0.f;

        #pragma unroll 1
        for (int kt = 0; kt < 4; ++kt) {
            uint2 bh[4];
            #pragma unroll
            for (int nt = 0; nt < 4; ++nt)
                bh[nt] = ((const uint2*)Bw)[(nt * 8 + kt) * 32 + (lane ^ (2 * nt + lq))];
            #pragma unroll
            for (int mt = 0; mt < 8; ++mt) {
                uint4 ah = A2[(mt * 4 + kt) * 32 + lane];
                #pragma unroll
                for (int nt = 0; nt < 4; ++nt) mma_f16(acc[mt][nt], ah, bh[nt]);
            }
        }
        #pragma unroll
        for (int nt = 0; nt < 4; ++nt) {
            int n0 = nb + nt * 8 + tig * 2, n1 = n0 + 1;
            #pragma unroll
            for (int mt = 0; mt < 8; ++mt) {
                int r0 = mt * 16 + gid, r1 = r0 + 8;
                if (n0 < n) {
                    g_Q[(size_t)n0 * H + r0] = __float2half_rn(acc[mt][nt][0]);
                    g_Q[(size_t)n0 * H + r1] = __float2half_rn(acc[mt][nt][2]);
                }
                if (n1 < n) {
                    g_Q[(size_t)n1 * H + r0] = __float2half_rn(acc[mt][nt][1]);
                    g_Q[(size_t)n1 * H + r1] = __float2half_rn(acc[mt][nt][3]);
                }
            }
        }
    }
}

// ---------------------------------------------------------------------------
// Edge kernel (R14 structure): coalesced gather + fp16 accumulators,
// 128-thread blocks, 3 blocks/SM. Staging unroll deepened to 8;
// epilogue constants read from smem (frees persistent regs).
// ---------------------------------------------------------------------------
#define E_A   0                 // 32 KB
#define E_B   32768             // 4 warps x 8 KB
#define E_B2S 65536
#define E_W3S 66048
#define EDGE_SMEM_BYTES 66560

__global__ void __launch_bounds__(128) edge_kernel(
    const int* __restrict__ src, const int* __restrict__ dst,
    const float* __restrict__ W2, const float* __restrict__ b2,
    const float* __restrict__ W3, const float* __restrict__ b3,
    float* __restrict__ out, int E, int n)
{
    extern __shared__ char smc[];
    uint4* Ahi = (uint4*)(smc + E_A);
    float* b2s = (float*)(smc + E_B2S);
    float* w3s = (float*)(smc + E_W3S);

    const int t = threadIdx.x, lane = t & 31, w = t >> 5;
    const int gid = lane >> 2, tig = lane & 3;

    if (blockIdx.x == 0 && t == 0) g_ctr_pre = 0;

    {
        float* scr = (float*)(smc + E_B);
        for (int chunk = 0; chunk < 4; ++chunk) {
            __syncthreads();
            for (int i = t; i < 1024; i += 128)
                ((float4*)scr)[i] = ((const float4*)W2)[chunk * 1024 + i];
            __syncthreads();
            build_frags_h(scr, Ahi, chunk * 2, 8, t, 128);
        }
    }
    b2s[t] = b2[t];
    w3s[t] = W3[t];
    __syncthreads();

    const float b3v = b3[0];

    uint32_t* Bw = (uint32_t*)(smc + E_B + w * 8192);
    const int lq = lane >> 4;
    const int chunk = lane & 15, half = lane >> 4;
    const int ntiles = (E + 31) >> 5;

    for (;;) {
        int tile;
        if (lane == 0) tile = atomicAdd(&g_ctr_edge, 1);
        tile = __shfl_sync(0xffffffffu, tile, 0);
        if (tile >= ntiles) break;
        const int e0 = tile * 32;

        // preload this lane's edge indices (lane = edge within tile);
        // OOB edges read node 0 (finite junk; columns discarded at output)
        int sA = 0, dA = 0;
        {
            int gl = e0 + lane;
            if (gl < E) {
                sA = min(max(src[gl], 0), n - 1);
                dA = min(max(dst[gl], 0), n - 1);
            }
        }
        __syncwarp();

        // coalesced staging: 16 passes x 2 edges; deeper unroll for MLP
        #pragma unroll 8
        for (int p = 0; p < 16; ++p) {
            int eo = 2 * p + half;
            int s = __shfl_sync(0xffffffffu, sA, eo);
            int d = __shfl_sync(0xffffffffu, dA, eo);
            uint4 pv = *(const uint4*)(g_P + (size_t)s * H + chunk * 8);
            uint4 qv = *(const uint4*)(g_Q + (size_t)d * H + chunk * 8);
            int nt = eo >> 3, nn = eo & 7, xe = eo >> 2;
            stage4x(Bw, nt, nn, xe, chunk * 8,
                    sigt2u(pv.x, qv.x), sigt2u(pv.y, qv.y));
            stage4x(Bw, nt, nn, xe, chunk * 8 + 4,
                    sigt2u(pv.z, qv.z), sigt2u(pv.w, qv.w));
        }
        __syncwarp();

        // MMA mainloop, fp16 accumulators (packed pairs)
        uint32_t acc[8][4][2];
        #pragma unroll
        for (int mt = 0; mt < 8; ++mt)
            #pragma unroll
            for (int nt = 0; nt < 4; ++nt) { acc[mt][nt][0] = 0u; acc[mt][nt][1] = 0u; }

        #pragma unroll 1
        for (int kt = 0; kt < 8; ++kt) {
            uint2 bh[4];
            #pragma unroll
            for (int nt = 0; nt < 4; ++nt)
                bh[nt] = ((const uint2*)Bw)[(nt * 8 + kt) * 32 +
                                            ((lane ^ (2 * nt + lq)) ^ (kt << 1))];
            #pragma unroll
            for (int mt = 0; mt < 8; ++mt) {
                uint4 ah = Ahi[(mt * 8 + kt) * 32 + lane];
                #pragma unroll
                for (int nt = 0; nt < 4; ++nt) mma_f16acc(acc[mt][nt], ah, bh[nt]);
            }
        }

        // epilogue (fp32 sigt; b2/W3 read from smem — low rate, saves regs)
        #pragma unroll
        for (int nt = 0; nt < 4; ++nt) {
            float s0 = 0.f, s1 = 0.f;
            #pragma unroll
            for (int mt = 0; mt < 8; ++mt) {
                int r0 = mt * 16 + gid, r1 = r0 + 8;
                float2 lo = h2f2u(acc[mt][nt][0]);
                float2 hi = h2f2u(acc[mt][nt][1]);
                s0 += sigt(lo.x + b2s[r0]) * w3s[r0]
                    + sigt(hi.x + b2s[r1]) * w3s[r1];
                s1 += sigt(lo.y + b2s[r0]) * w3s[r0]
                    + sigt(hi.y + b2s[r1]) * w3s[r1];
            }
            #pragma unroll
            for (int off = 4; off <= 16; off <<= 1) {
                s0 += __shfl_xor_sync(0xffffffffu, s0, off);
                s1 += __shfl_xor_sync(0xffffffffu, s1, off);
            }
            if (gid == 0) {
                int go = e0 + nt * 8 + tig * 2;
                if (go + 1 < E)
                    *(float2*)(out + go) = make_float2(s0 + b3v, s1 + b3v);
                else if (go < E)
                    out[go] = s0 + b3v;
            }
        }
    }
}

extern "C" void kernel_launch(void* const* d_in, const int* in_sizes, int n_in,
                              void* d_out, int out_size)
{
    const float* h1 = (const float*)d_in[0];
    const float* h2 = (const float*)d_in[1];
    const int* src = (const int*)d_in[2];
    const int* dst = (const int*)d_in[3];
    const float* W1 = (const float*)d_in[4];
    const float* b1 = (const float*)d_in[5];
    const float* W2 = (const float*)d_in[6];
    const float* b2 = (const float*)d_in[7];
    const float* W3 = (const float*)d_in[8];
    const float* b3 = (const float*)d_in[9];
    float* out = (float*)d_out;

    const int n = in_sizes[0] / D;
    const int E = in_sizes[2];

    cudaFuncSetAttribute(precompute_kernel,
                         cudaFuncAttributeMaxDynamicSharedMemorySize, PRE_SMEM_BYTES);
    cudaFuncSetAttribute(edge_kernel,
                         cudaFuncAttributeMaxDynamicSharedMemorySize, EDGE_SMEM_BYTES);

    precompute_kernel<<<148, 256, PRE_SMEM_BYTES>>>(h1, h2, W1, b1, n);
    edge_kernel<<<444, 128, EDGE_SMEM_BYTES>>>(src, dst, W2, b2, W3, b3, out, E, n);
}

// round 16
// speedup vs baseline: 1.3596x; 1.0041x over previous
#include <cuda_runtime.h>
#include <cuda_fp16.h>
#include <cstdint>

#define D 64
#define H 128
#define NMAX 50048

__device__ __align__(16) __half g_P[(size_t)NMAX * H];
__device__ __align__(16) __half g_Q[(size_t)NMAX * H];
__device__ int g_ctr_pre;    // reset by edge_kernel (for next replay)
__device__ int g_ctr_edge;   // reset by precompute_kernel (runs first)

__device__ __forceinline__ float sigt(float x) {
    float t;
    asm("tanh.approx.f32 %0, %1;" : "=f"(t) : "f"(x * 0.5f));
    return fmaf(t, 0.5f, 0.5f);
}
__device__ __forceinline__ uint32_t sigt2u(uint32_t p, uint32_t q) {
    __half2 x = __hadd2(*(__half2*)&p, *(__half2*)&q);
    const __half2 hhalf = __floats2half2_rn(0.5f, 0.5f);
    __half2 xh = __hmul2(x, hhalf);
    uint32_t tu;
    asm("tanh.approx.f16x2 %0, %1;" : "=r"(tu) : "r"(*(uint32_t*)&xh));
    __half2 r = __hfma2(*(__half2*)&tu, hhalf, hhalf);
    return *(uint32_t*)&r;
}
__device__ __forceinline__ uint32_t f16x2(float lo, float hi) {
    __half2 h = __floats2half2_rn(lo, hi);
    return *(uint32_t*)&h;
}
__device__ __forceinline__ float2 h2f2u(uint32_t u) {
    return __half22float2(*(__half2*)&u);
}

// fp32-acc MMA (precompute — P/Q accuracy matters)
__device__ __forceinline__ void mma_f16(float* c, uint4 a, uint2 b) {
    asm volatile(
        "mma.sync.aligned.m16n8k16.row.col.f32.f16.f16.f32 "
        "{%0,%1,%2,%3}, {%4,%5,%6,%7}, {%8,%9}, {%0,%1,%2,%3};"
        : "+f"(c[0]), "+f"(c[1]), "+f"(c[2]), "+f"(c[3])
        : "r"(a.x), "r"(a.y), "r"(a.z), "r"(a.w), "r"(b.x), "r"(b.y));
}
// fp16-acc MMA (edge layer-2 — halves accumulator registers; R14 win)
__device__ __forceinline__ void mma_f16acc(uint32_t* c, uint4 a, uint2 b) {
    asm volatile(
        "mma.sync.aligned.m16n8k16.row.col.f16.f16.f16.f16 "
        "{%0,%1}, {%2,%3,%4,%5}, {%6,%7}, {%0,%1};"
        : "+r"(c[0]), "+r"(c[1])
        : "r"(a.x), "r"(a.y), "r"(a.z), "r"(a.w), "r"(b.x), "r"(b.y));
}

// Build fp16 A-fragments (m16n8k16 row-major layout, validated R5-R15).
__device__ __forceinline__ void build_frags_h(const float* scr, uint4* A,
                                              int mt_base, int nkt, int t, int nth)
{
    const int ncols = nkt * 16;
    for (int fid = t; fid < 64 * nkt; fid += nth) {
        int fl = fid & 31;
        int kt = (fid >> 5) % nkt;
        int mtl = fid / (32 * nkt);
        int fg = fl >> 2, ft = fl & 3;
        int lr0 = mtl * 16 + fg, lr1 = lr0 + 8;
        int k0 = kt * 16 + ft * 2;
        uint4 hi;
        hi.x = f16x2(scr[lr0 * ncols + k0],     scr[lr0 * ncols + k0 + 1]);
        hi.y = f16x2(scr[lr1 * ncols + k0],     scr[lr1 * ncols + k0 + 1]);
        hi.z = f16x2(scr[lr0 * ncols + k0 + 8], scr[lr0 * ncols + k0 + 9]);
        hi.w = f16x2(scr[lr1 * ncols + k0 + 8], scr[lr1 * ncols + k0 + 9]);
        A[((mt_base + mtl) * nkt + kt) * 32 + fl] = hi;
    }
}

// Legacy staging (precompute, R13-proven): writer XOR = e>>2; reader
// lane ^ (2*nt+lq), no kt word-swizzle.
__device__ __forceinline__ void stage4h(uint32_t* B, int nt, int nn, int xe, int k,
                                        float z0, float z1, float z2, float z3)
{
    uint32_t h01 = f16x2(z0, z1);
    uint32_t h23 = f16x2(z2, z3);
    int kt = k >> 4, kq = (k & 7) >> 1, reg = (k >> 3) & 1;
    int l0 = (nn * 4 + kq) ^ xe, l1 = (nn * 4 + kq + 1) ^ xe;
    int base = (nt * 8 + kt) * 64;
    B[base + l0 * 2 + reg] = h01;
    B[base + l1 * 2 + reg] = h23;
}

// Coalesced staging store (edge, R13-R15 validated): word swizzle ^(kt<<2);
// readers compensate with ^(kt<<1) on their uint2 index.
__device__ __forceinline__ void stage4x(uint32_t* Bw, int nt, int nn, int xe,
                                        int k, uint32_t w01, uint32_t w23)
{
    int kt = k >> 4, kq = (k & 7) >> 1, reg = (k >> 3) & 1, wx = kt << 2;
    uint32_t* slab = Bw + (nt * 8 + kt) * 64;
    slab[((((nn * 4 + kq) ^ xe) << 1) + reg) ^ wx] = w01;
    slab[((((nn * 4 + kq + 1) ^ xe) << 1) + reg) ^ wx] = w23;
}

// ---------------------------------------------------------------------------
// Precompute (R13 version verbatim — known good)
// ---------------------------------------------------------------------------
#define P_A1 0
#define P_A2 32768
#define P_B  49152
#define P_B1S 114688
#define PRE_SMEM_BYTES 115712

__global__ void __launch_bounds__(256) precompute_kernel(
    const float* __restrict__ h1, const float* __restrict__ h2,
    const float* __restrict__ W1, const float* __restrict__ b1, int n)
{
    extern __shared__ char smc[];
    uint4* A1 = (uint4*)(smc + P_A1);
    uint4* A2 = (uint4*)(smc + P_A2);
    float* b1s = (float*)(smc + P_B1S);

    const int t = threadIdx.x, lane = t & 31, w = t >> 5;
    const int gid = lane >> 2, tig = lane & 3;

    if (blockIdx.x == 0 && t == 0) g_ctr_edge = 0;

    {
        float* scr = (float*)(smc + P_B);
        for (int chunk = 0; chunk < 4; ++chunk) {
            const int R0 = chunk * 32;
            __syncthreads();
            for (int idx = t; idx < 4096; idx += 256) {
                int r = idx >> 7, k = idx & 127;
                float v;
                if (k < 64) v = W1[(R0 + r) * 256 + k];
                else        v = W1[(R0 + r) * 256 + 64 + k] + W1[(R0 + r) * 256 + 128 + k];
                scr[r * 128 + k] = v;
            }
            __syncthreads();
            build_frags_h(scr, A1, chunk * 2, 8, t, 256);
        }
        for (int chunk = 0; chunk < 4; ++chunk) {
            const int R0 = chunk * 32;
            __syncthreads();
            for (int idx = t; idx < 2048; idx += 256) {
                int r = idx >> 6, k = idx & 63;
                scr[r * 64 + k] = W1[(R0 + r) * 256 + 64 + k];
            }
            __syncthreads();
            build_frags_h(scr, A2, chunk * 2, 4, t, 256);
        }
    }
    if (t < 128) b1s[t] = b1[t];
    __syncthreads();

    float b1r0[8], b1r1[8];
    #pragma unroll
    for (int mt = 0; mt < 8; ++mt) {
        b1r0[mt] = b1s[mt * 16 + gid];
        b1r1[mt] = b1s[mt * 16 + gid + 8];
    }

    uint32_t* Bw = (uint32_t*)(smc + P_B + w * 8192);
    const int e = lane, nt_e = e >> 3, n_e = e & 7, xe = e >> 2;
    const int lq = lane >> 4;
    const int ntiles = (n + 31) >> 5;

    for (;;) {
        int tile;
        if (lane == 0) tile = atomicAdd(&g_ctr_pre, 1);
        tile = __shfl_sync(0xffffffffu, tile, 0);
        if (tile >= ntiles) break;
        const int nb = tile * 32;
        const int node = nb + e;
        __syncwarp();

        if (node < n) {
            const float4* H1 = (const float4*)(h1 + (size_t)node * D);
            const float4* H2 = (const float4*)(h2 + (size_t)node * D);
            #pragma unroll 8
            for (int u = 0; u < 16; ++u) {
                float4 v = H1[u];
                stage4h(Bw, nt_e, n_e, xe, u * 4, v.x, v.y, v.z, v.w);
            }
            #pragma unroll 8
            for (int u = 0; u < 16; ++u) {
                float4 v = H2[u];
                stage4h(Bw, nt_e, n_e, xe, 64 + u * 4, v.x, v.y, v.z, v.w);
            }
        } else {
            #pragma unroll 8
            for (int u = 0; u < 32; ++u)
                stage4h(Bw, nt_e, n_e, xe, u * 4, 0.f, 0.f, 0.f, 0.f);
        }
        __syncwarp();

        float acc[8][4][4];

        #pragma unroll
        for (int mt = 0; mt < 8; ++mt)
            #pragma unroll
            for (int nt = 0; nt < 4; ++nt)
                #pragma unroll
                for (int r = 0; r < 4; ++r) acc[mt][nt][r] = 0.f;

        #pragma unroll 1
        for (int kt = 0; kt < 8; ++kt) {
            uint2 bh[4];
            #pragma unroll
            for (int nt = 0; nt < 4; ++nt)
                bh[nt] = ((const uint2*)Bw)[(nt * 8 + kt) * 32 + (lane ^ (2 * nt + lq))];
            #pragma unroll
            for (int mt = 0; mt < 8; ++mt) {
                uint4 ah = A1[(mt * 8 + kt) * 32 + lane];
                #pragma unroll
                for (int nt = 0; nt < 4; ++nt) mma_f16(acc[mt][nt], ah, bh[nt]);
            }
        }
        #pragma unroll
        for (int nt = 0; nt < 4; ++nt) {
            int n0 = nb + nt * 8 + tig * 2, n1 = n0 + 1;
            #pragma unroll
            for (int mt = 0; mt < 8; ++mt) {
                int r0 = mt * 16 + gid, r1 = r0 + 8;
                if (n0 < n) {
                    g_P[(size_t)n0 * H + r0] = __float2half_rn(acc[mt][nt][0] + b1r0[mt]);
                    g_P[(size_t)n0 * H + r1] = __float2half_rn(acc[mt][nt][2] + b1r1[mt]);
                }
                if (n1 < n) {
                    g_P[(size_t)n1 * H + r0] = __float2half_rn(acc[mt][nt][1] + b1r0[mt]);
                    g_P[(size_t)n1 * H + r1] = __float2half_rn(acc[mt][nt][3] + b1r1[mt]);
                }
            }
        }

        #pragma unroll
        for (int mt = 0; mt < 8; ++mt)
            #pragma unroll
            for (int nt = 0; nt < 4; ++nt)
                #pragma unroll
                for (int r = 0; r < 4; ++r) acc[mt][nt][r] = 0.f;

        #pragma unroll 1
        for (int kt = 0; kt < 4; ++kt) {
            uint2 bh[4];
            #pragma unroll
            for (int nt = 0; nt < 4; ++nt)
                bh[nt] = ((const uint2*)Bw)[(nt * 8 + kt) * 32 + (lane ^ (2 * nt + lq))];
            #pragma unroll
            for (int mt = 0; mt < 8; ++mt) {
                uint4 ah = A2[(mt * 4 + kt) * 32 + lane];
                #pragma unroll
                for (int nt = 0; nt < 4; ++nt) mma_f16(acc[mt][nt], ah, bh[nt]);
            }
        }
        #pragma unroll
        for (int nt = 0; nt < 4; ++nt) {
            int n0 = nb + nt * 8 + tig * 2, n1 = n0 + 1;
            #pragma unroll
            for (int mt = 0; mt < 8; ++mt) {
                int r0 = mt * 16 + gid, r1 = r0 + 8;
                if (n0 < n) {
                    g_Q[(size_t)n0 * H + r0] = __float2half_rn(acc[mt][nt][0]);
                    g_Q[(size_t)n0 * H + r1] = __float2half_rn(acc[mt][nt][2]);
                }
                if (n1 < n) {
                    g_Q[(size_t)n1 * H + r0] = __float2half_rn(acc[mt][nt][1]);
                    g_Q[(size_t)n1 * H + r1] = __float2half_rn(acc[mt][nt][3]);
                }
            }
        }
    }
}

// ---------------------------------------------------------------------------
// Edge kernel: R15 per-warp structure, 256-thread blocks (8 warps share one
// 32KB A table) -> 97.5KB smem, 2 blocks/SM, 16 warps/SM (regs must stay <=128).
// ---------------------------------------------------------------------------
#define E_A   0                 // 32 KB
#define E_B   32768             // 8 warps x 8 KB
#define E_B2S 98304
#define E_W3S 98816
#define EDGE_SMEM_BYTES 99840

__global__ void __launch_bounds__(256) edge_kernel(
    const int* __restrict__ src, const int* __restrict__ dst,
    const float* __restrict__ W2, const float* __restrict__ b2,
    const float* __restrict__ W3, const float* __restrict__ b3,
    float* __restrict__ out, int E, int n)
{
    extern __shared__ char smc[];
    uint4* Ahi = (uint4*)(smc + E_A);
    float* b2s = (float*)(smc + E_B2S);
    float* w3s = (float*)(smc + E_W3S);

    const int t = threadIdx.x, lane = t & 31, w = t >> 5;
    const int gid = lane >> 2, tig = lane & 3;

    if (blockIdx.x == 0 && t == 0) g_ctr_pre = 0;

    {
        float* scr = (float*)(smc + E_B);
        for (int chunk = 0; chunk < 4; ++chunk) {
            __syncthreads();
            for (int i = t; i < 1024; i += 256)
                ((float4*)scr)[i] = ((const float4*)W2)[chunk * 1024 + i];
            __syncthreads();
            build_frags_h(scr, Ahi, chunk * 2, 8, t, 256);
        }
    }
    if (t < 128) { b2s[t] = b2[t]; w3s[t] = W3[t]; }
    __syncthreads();

    const float b3v = b3[0];

    uint32_t* Bw = (uint32_t*)(smc + E_B + w * 8192);
    const int lq = lane >> 4;
    const int chunk = lane & 15, half = lane >> 4;
    const int ntiles = (E + 31) >> 5;

    for (;;) {
        int tile;
        if (lane == 0) tile = atomicAdd(&g_ctr_edge, 1);
        tile = __shfl_sync(0xffffffffu, tile, 0);
        if (tile >= ntiles) break;
        const int e0 = tile * 32;

        // preload this lane's edge indices (lane = edge within tile);
        // OOB edges read node 0 (finite junk; columns discarded at output)
        int sA = 0, dA = 0;
        {
            int gl = e0 + lane;
            if (gl < E) {
                sA = min(max(src[gl], 0), n - 1);
                dA = min(max(dst[gl], 0), n - 1);
            }
        }
        __syncwarp();

        // coalesced staging: 16 passes x 2 edges (4 lines per LDG.128)
        #pragma unroll 8
        for (int p = 0; p < 16; ++p) {
            int eo = 2 * p + half;
            int s = __shfl_sync(0xffffffffu, sA, eo);
            int d = __shfl_sync(0xffffffffu, dA, eo);
            uint4 pv = *(const uint4*)(g_P + (size_t)s * H + chunk * 8);
            uint4 qv = *(const uint4*)(g_Q + (size_t)d * H + chunk * 8);
            int nt = eo >> 3, nn = eo & 7, xe = eo >> 2;
            stage4x(Bw, nt, nn, xe, chunk * 8,
                    sigt2u(pv.x, qv.x), sigt2u(pv.y, qv.y));
            stage4x(Bw, nt, nn, xe, chunk * 8 + 4,
                    sigt2u(pv.z, qv.z), sigt2u(pv.w, qv.w));
        }
        __syncwarp();

        // MMA mainloop, fp16 accumulators (packed pairs)
        uint32_t acc[8][4][2];
        #pragma unroll
        for (int mt = 0; mt < 8; ++mt)
            #pragma unroll
            for (int nt = 0; nt < 4; ++nt) { acc[mt][nt][0] = 0u; acc[mt][nt][1] = 0u; }

        #pragma unroll 1
        for (int kt = 0; kt < 8; ++kt) {
            uint2 bh[4];
            #pragma unroll
            for (int nt = 0; nt < 4; ++nt)
                bh[nt] = ((const uint2*)Bw)[(nt * 8 + kt) * 32 +
                                            ((lane ^ (2 * nt + lq)) ^ (kt << 1))];
            #pragma unroll
            for (int mt = 0; mt < 8; ++mt) {
                uint4 ah = Ahi[(mt * 8 + kt) * 32 + lane];
                #pragma unroll
                for (int nt = 0; nt < 4; ++nt) mma_f16acc(acc[mt][nt], ah, bh[nt]);
            }
        }

        // epilogue (fp32 sigt; b2/W3 from smem — low rate, saves regs)
        #pragma unroll
        for (int nt = 0; nt < 4; ++nt) {
            float s0 = 0.f, s1 = 0.f;
            #pragma unroll
            for (int mt = 0; mt < 8; ++mt) {
                int r0 = mt * 16 + gid, r1 = r0 + 8;
                float2 lo = h2f2u(acc[mt][nt][0]);
                float2 hi = h2f2u(acc[mt][nt][1]);
                s0 += sigt(lo.x + b2s[r0]) * w3s[r0]
                    + sigt(hi.x + b2s[r1]) * w3s[r1];
                s1 += sigt(lo.y + b2s[r0]) * w3s[r0]
                    + sigt(hi.y + b2s[r1]) * w3s[r1];
            }
            #pragma unroll
            for (int off = 4; off <= 16; off <<= 1) {
                s0 += __shfl_xor_sync(0xffffffffu, s0, off);
                s1 += __shfl_xor_sync(0xffffffffu, s1, off);
            }
            if (gid == 0) {
                int go = e0 + nt * 8 + tig * 2;
                if (go + 1 < E)
                    *(float2*)(out + go) = make_float2(s0 + b3v, s1 + b3v);
                else if (go < E)
                    out[go] = s0 + b3v;
            }
        }
    }
}

extern "C" void kernel_launch(void* const* d_in, const int* in_sizes, int n_in,
                              void* d_out, int out_size)
{
    const float* h1 = (const float*)d_in[0];
    const float* h2 = (const float*)d_in[1];
    const int* src = (const int*)d_in[2];
    const int* dst = (const int*)d_in[3];
    const float* W1 = (const float*)d_in[4];
    const float* b1 = (const float*)d_in[5];
    const float* W2 = (const float*)d_in[6];
    const float* b2 = (const float*)d_in[7];
    const float* W3 = (const float*)d_in[8];
    const float* b3 = (const float*)d_in[9];
    float* out = (float*)d_out;

    const int n = in_sizes[0] / D;
    const int E = in_sizes[2];

    cudaFuncSetAttribute(precompute_kernel,
                         cudaFuncAttributeMaxDynamicSharedMemorySize, PRE_SMEM_BYTES);
    cudaFuncSetAttribute(edge_kernel,
                         cudaFuncAttributeMaxDynamicSharedMemorySize, EDGE_SMEM_BYTES);

    precompute_kernel<<<148, 256, PRE_SMEM_BYTES>>>(h1, h2, W1, b1, n);
    edge_kernel<<<296, 256, EDGE_SMEM_BYTES>>>(src, dst, W2, b2, W3, b3, out, E, n);
}